// round 13
// baseline (speedup 1.0000x reference)
#include <cuda_runtime.h>
#include <cuda_fp16.h>
#include <math.h>
#include <stdint.h>

// Problem dims (fixed): B=8192, K(=D=H)=1024, 4H=4096
#define BATCH 8192
#define KDIM  1024
#define GDIM  4096

// ---------------------------------------------------------------------------
// Device-global scratch (allocation-free rule)
// ---------------------------------------------------------------------------
__device__ __half g_gh[(size_t)BATCH * GDIM];   // h0 @ Wh (fp16 storage)
__device__ __half g_gx[(size_t)BATCH * GDIM];   // x  @ Wx (fp16 storage)

__device__ __half g_h0f[(size_t)BATCH * KDIM];
__device__ __half g_xf [(size_t)BATCH * KDIM];
__device__ __half g_whf[(size_t)GDIM * KDIM];   // Wt [N][K]
__device__ __half g_wxf[(size_t)GDIM * KDIM];
__device__ float  g_bsum[GDIM];                 // ln1b + ln2b + bias

// ---------------------------------------------------------------------------
// Single merged conversion kernel: 1D grid dispatch.
//   blocks [0, 8192)        : h0 -> g_h0f
//   blocks [8192, 16384)    : x  -> g_xf
//   blocks [16384, 17408)   : Wh -> g_whf (transpose 64x64 tiles)
//   blocks [17408, 18432)   : Wx -> g_wxf
//   blocks [18432, 18436)   : bsum = ln1b + ln2b + bias
// ---------------------------------------------------------------------------
#define ACT_BLOCKS 8192
#define WT_BLOCKS  1024
#define CV_BLOCKS  (2 * ACT_BLOCKS + 2 * WT_BLOCKS + 4)

__global__ __launch_bounds__(256)
void convert_all(const float* __restrict__ h0, const float* __restrict__ x,
                 const float* __restrict__ Wh, const float* __restrict__ Wx,
                 const float* __restrict__ ln1b, const float* __restrict__ ln2b,
                 const float* __restrict__ bias)
{
    __shared__ float tile[64][65];
    const int bx = blockIdx.x;
    const int tid = threadIdx.x;

    if (bx < 2 * ACT_BLOCKS) {
        const float* src = (bx < ACT_BLOCKS) ? h0 : x;
        __half* dst = (bx < ACT_BLOCKS) ? g_h0f : g_xf;
        int blk = (bx < ACT_BLOCKS) ? bx : bx - ACT_BLOCKS;
        size_t i = ((size_t)blk * 256 + tid) * 4;
        float4 v = *reinterpret_cast<const float4*>(src + i);
        *reinterpret_cast<__half2*>(dst + i)     = __floats2half2_rn(v.x, v.y);
        *reinterpret_cast<__half2*>(dst + i + 2) = __floats2half2_rn(v.z, v.w);
        return;
    }

    if (bx >= 2 * ACT_BLOCKS + 2 * WT_BLOCKS) {
        int i = (bx - (2 * ACT_BLOCKS + 2 * WT_BLOCKS)) * 1024 + tid * 4;
        float4 a = *reinterpret_cast<const float4*>(ln1b + i);
        float4 b = *reinterpret_cast<const float4*>(ln2b + i);
        float4 c = *reinterpret_cast<const float4*>(bias + i);
        float4 s = make_float4(a.x + b.x + c.x, a.y + b.y + c.y,
                               a.z + b.z + c.z, a.w + b.w + c.w);
        *reinterpret_cast<float4*>(g_bsum + i) = s;
        return;
    }

    const int wtb = bx - 2 * ACT_BLOCKS;
    const float* W = (wtb < WT_BLOCKS) ? Wh : Wx;
    __half* T = (wtb < WT_BLOCKS) ? g_whf : g_wxf;
    const int t = (wtb < WT_BLOCKS) ? wtb : wtb - WT_BLOCKS;
    const int n0 = (t & 63) * 64;
    const int k0 = (t >> 6) * 64;

    #pragma unroll
    for (int it = 0; it < 4; it++) {
        int i = tid + it * 256;
        int r = i >> 4;
        int c4 = i & 15;
        float4 v = *reinterpret_cast<const float4*>(
            &W[(size_t)(k0 + r) * GDIM + n0 + c4 * 4]);
        tile[r][c4 * 4 + 0] = v.x;
        tile[r][c4 * 4 + 1] = v.y;
        tile[r][c4 * 4 + 2] = v.z;
        tile[r][c4 * 4 + 3] = v.w;
    }
    __syncthreads();
    #pragma unroll
    for (int it = 0; it < 8; it++) {
        int i = tid + it * 256;
        int n = i >> 5;
        int k2 = i & 31;
        __half2 hv = __floats2half2_rn(tile[k2 * 2][n], tile[k2 * 2 + 1][n]);
        *reinterpret_cast<__half2*>(&T[(size_t)(n0 + n) * KDIM + k0 + k2 * 2]) = hv;
    }
}

// ---------------------------------------------------------------------------
// mma.sync fp16 GEMM (best measured config): CTA 128x128, 8 warps (32x64),
// BK=64, 3-stage cp.async, ONE barrier per iter, 2 CTAs/SM.
// R13: first LDSM batch issued before next-stage cp.async burst.
// ---------------------------------------------------------------------------
#define BM 128
#define BN 128
#define BK 64
#define KTILES (KDIM / BK)      // 16
#define NTHREADS 256
#define NSTAGES 3

#define ROWB 144
#define T_A 0
#define T_B (128 * ROWB)
#define STAGE (2 * 128 * ROWB)   // 36864
#define SMEM_TOTAL (NSTAGES * STAGE)   // 110592 -> 2 CTAs/SM

__device__ __forceinline__ uint32_t smem_u32(const void* p) {
    return (uint32_t)__cvta_generic_to_shared(p);
}
__device__ __forceinline__ void cp16(uint32_t dst, const void* src) {
    asm volatile("cp.async.cg.shared.global [%0], [%1], 16;\n" :: "r"(dst), "l"(src));
}
__device__ __forceinline__ void ldsm4(uint32_t* r, uint32_t addr) {
    asm volatile("ldmatrix.sync.aligned.m8n8.x4.shared.b16 {%0,%1,%2,%3}, [%4];\n"
                 : "=r"(r[0]), "=r"(r[1]), "=r"(r[2]), "=r"(r[3]) : "r"(addr));
}
__device__ __forceinline__ void mma16816(float* d, const uint32_t* a, const uint32_t* b) {
    asm volatile(
        "mma.sync.aligned.m16n8k16.row.col.f32.f16.f16.f32 "
        "{%0,%1,%2,%3}, {%4,%5,%6,%7}, {%8,%9}, {%0,%1,%2,%3};\n"
        : "+f"(d[0]), "+f"(d[1]), "+f"(d[2]), "+f"(d[3])
        : "r"(a[0]), "r"(a[1]), "r"(a[2]), "r"(a[3]), "r"(b[0]), "r"(b[1]));
}

__device__ __forceinline__ void load_stage(uint32_t sb, int buf,
                                           const __half* A, const __half* B,
                                           int mBase, int nBase, int k0, int tid)
{
    uint32_t st = sb + buf * STAGE;
    #pragma unroll
    for (int it = 0; it < 2048 / NTHREADS; it++) {
        int i = tid + it * NTHREADS;
        int t = i >> 10;
        int j = i & 1023;
        int row = j >> 3;
        int c = j & 7;
        const __half* src;
        uint32_t toff;
        if (t == 0) { src = A + (size_t)(mBase + row) * KDIM + k0 + c * 8; toff = T_A; }
        else        { src = B + (size_t)(nBase + row) * KDIM + k0 + c * 8; toff = T_B; }
        cp16(st + toff + (uint32_t)(row * ROWB + c * 16), src);
    }
}

#define LOAD_B(p, ksv, hv) do {                                                   \
    uint32_t r[4];                                                                \
    ldsm4(r, st + T_B + bOff + (uint32_t)(((hv) * 2 + 0) * 16 * ROWB) + (ksv) * 32); \
    bf[p][0][0] = r[0]; bf[p][0][1] = r[1]; bf[p][1][0] = r[2]; bf[p][1][1] = r[3]; \
    ldsm4(r, st + T_B + bOff + (uint32_t)(((hv) * 2 + 1) * 16 * ROWB) + (ksv) * 32); \
    bf[p][2][0] = r[0]; bf[p][2][1] = r[1]; bf[p][3][0] = r[2]; bf[p][3][1] = r[3]; \
} while (0)

__global__ __launch_bounds__(NTHREADS, 2)
void gemm_mma()
{
    extern __shared__ char smem[];
    const int which = blockIdx.z;
    const __half *A, *B;
    __half* C;
    if (which == 0) { A = g_h0f; B = g_whf; C = g_gh; }
    else            { A = g_xf;  B = g_wxf; C = g_gx; }

    const int nBase = blockIdx.x * BN;
    const int mBase = blockIdx.y * BM;
    const int tid  = threadIdx.x;
    const int lane = tid & 31;
    const int wid  = tid >> 5;
    const int wm   = wid & 3;
    const int wn   = wid >> 2;
    uint32_t sb = smem_u32(smem);

    const uint32_t aOff = (uint32_t)((wm * 32 + (lane & 15)) * ROWB + (lane >> 4) * 16);
    const uint32_t bRow = (uint32_t)(wn * 64 + ((lane >> 4) << 3) + (lane & 7));
    const uint32_t bOff = bRow * ROWB + ((lane >> 3) & 1) * 16;

    float acc[2][8][4];
    #pragma unroll
    for (int mi = 0; mi < 2; mi++)
        #pragma unroll
        for (int ni = 0; ni < 8; ni++)
            #pragma unroll
            for (int q = 0; q < 4; q++)
                acc[mi][ni][q] = 0.0f;

    load_stage(sb, 0, A, B, mBase, nBase, 0,  tid);
    asm volatile("cp.async.commit_group;" ::: "memory");
    load_stage(sb, 1, A, B, mBase, nBase, BK, tid);
    asm volatile("cp.async.commit_group;" ::: "memory");

    int buf = 0;
    for (int k = 0; k < KTILES; k++) {
        if (k < KTILES - 1)
            asm volatile("cp.async.wait_group 1;" ::: "memory");
        else
            asm volatile("cp.async.wait_group 0;" ::: "memory");
        __syncthreads();

        uint32_t st = sb + buf * STAGE;

        uint32_t af[2][2][4];
        uint32_t bf[2][4][2];

        // Start filling fragments BEFORE issuing the next cp.async burst,
        // so the tensor pipe can begin sooner this iteration.
        ldsm4(af[0][0], st + T_A + aOff);
        ldsm4(af[0][1], st + T_A + aOff + 16 * ROWB);
        LOAD_B(0, 0, 0);

        if (k + 2 < KTILES) {
            int nb = buf + 2; if (nb >= 3) nb -= 3;
            load_stage(sb, nb, A, B, mBase, nBase, (k + 2) * BK, tid);
            asm volatile("cp.async.commit_group;" ::: "memory");
        }

        #pragma unroll
        for (int s = 0; s < 8; s++) {
            const int ks = s >> 1;
            const int h  = s & 1;
            const int cur = s & 1;
            if (s < 7)
                LOAD_B((s + 1) & 1, (s + 1) >> 1, (s + 1) & 1);
            if (h == 0 && ks < 3) {
                ldsm4(af[(ks + 1) & 1][0], st + T_A + aOff + (ks + 1) * 32);
                ldsm4(af[(ks + 1) & 1][1], st + T_A + aOff + 16 * ROWB + (ks + 1) * 32);
            }
            #pragma unroll
            for (int mi = 0; mi < 2; mi++)
                #pragma unroll
                for (int nj = 0; nj < 4; nj++)
                    mma16816(acc[mi][h * 4 + nj], af[ks & 1][mi], bf[cur][nj]);
        }

        buf++; if (buf >= 3) buf -= 3;
    }

    #pragma unroll
    for (int mi = 0; mi < 2; mi++) {
        #pragma unroll
        for (int ni = 0; ni < 8; ni++) {
            int row = mBase + wm * 32 + mi * 16 + (lane >> 2);
            int col = nBase + wn * 64 + ni * 8 + (lane & 3) * 2;
            __half2 v0 = __floats2half2_rn(acc[mi][ni][0], acc[mi][ni][1]);
            __half2 v1 = __floats2half2_rn(acc[mi][ni][2], acc[mi][ni][3]);
            *reinterpret_cast<__half2*>(C + (size_t)row * GDIM + col) = v0;
            *reinterpret_cast<__half2*>(C + (size_t)(row + 8) * GDIM + col) = v1;
        }
    }
}

// ---------------------------------------------------------------------------
// Fused LSTM epilogue: 2 rows/block, 1 barrier per reduction, tanh.approx,
// folded bias (bsum) -> 3 param arrays instead of 5.
// ---------------------------------------------------------------------------
__device__ __forceinline__ float tanh_fast(float x) {
    float y;
    asm("tanh.approx.f32 %0, %1;" : "=f"(y) : "f"(x));
    return y;
}
__device__ __forceinline__ float sigmoid_fast(float x) {
    return fmaf(0.5f, tanh_fast(0.5f * x), 0.5f);
}

__device__ __forceinline__ float4 warp_reduce4(float4 v) {
    #pragma unroll
    for (int o = 16; o > 0; o >>= 1) {
        v.x += __shfl_down_sync(0xffffffffu, v.x, o);
        v.y += __shfl_down_sync(0xffffffffu, v.y, o);
        v.z += __shfl_down_sync(0xffffffffu, v.z, o);
        v.w += __shfl_down_sync(0xffffffffu, v.w, o);
    }
    return v;
}

__global__ __launch_bounds__(256, 4)
void epilogue_kernel(const float* __restrict__ c0,
                     const float* __restrict__ ln1g,
                     const float* __restrict__ ln2g,
                     const float* __restrict__ ln3g, const float* __restrict__ ln3b,
                     float* __restrict__ h1, float* __restrict__ c1)
{
    __shared__ __half sgh[2][GDIM];
    __shared__ __half sgx[2][GDIM];
    __shared__ float4 red[2][4];
    __shared__ float4 red3[2][4];

    const int tid  = threadIdx.x;
    const int wg   = tid >> 7;
    const int wtid = tid & 127;
    const int lane = tid & 31;
    const int wrp  = wtid >> 5;
    const int b    = blockIdx.x * 2 + wg;

    const uint4* __restrict__ ghr = reinterpret_cast<const uint4*>(g_gh + (size_t)b * GDIM);
    const uint4* __restrict__ gxr = reinterpret_cast<const uint4*>(g_gx + (size_t)b * GDIM);

    const float EPS = 1e-5f;

    float4 st = make_float4(0.f, 0.f, 0.f, 0.f);
    #pragma unroll
    for (int it = 0; it < 4; it++) {
        int i = wtid + it * 128;
        uint4 v = ghr[i];
        uint4 w = gxr[i];
        *reinterpret_cast<uint4*>(&sgh[wg][i * 8]) = v;
        *reinterpret_cast<uint4*>(&sgx[wg][i * 8]) = w;
        const __half2* vh = reinterpret_cast<const __half2*>(&v);
        const __half2* wh = reinterpret_cast<const __half2*>(&w);
        #pragma unroll
        for (int q = 0; q < 4; q++) {
            float2 a = __half22float2(vh[q]);
            float2 bb = __half22float2(wh[q]);
            st.x += a.x + a.y;
            st.y += a.x * a.x + a.y * a.y;
            st.z += bb.x + bb.y;
            st.w += bb.x * bb.x + bb.y * bb.y;
        }
    }
    st = warp_reduce4(st);
    if (lane == 0) red[wg][wrp] = st;
    __syncthreads();
    {
        float4 a0 = red[wg][0], a1 = red[wg][1], a2 = red[wg][2], a3 = red[wg][3];
        st = make_float4(a0.x + a1.x + a2.x + a3.x, a0.y + a1.y + a2.y + a3.y,
                         a0.z + a1.z + a2.z + a3.z, a0.w + a1.w + a2.w + a3.w);
    }
    const float inv4h = 1.0f / (float)GDIM;
    float mu1 = st.x * inv4h;
    float rs1 = rsqrtf(fmaxf(st.y * inv4h - mu1 * mu1, 0.f) + EPS);
    float mu2 = st.z * inv4h;
    float rs2 = rsqrtf(fmaxf(st.w * inv4h - mu2 * mu2, 0.f) + EPS);

    float c1v[8], ogv[8];
    float4 st3 = make_float4(0.f, 0.f, 0.f, 0.f);
    #pragma unroll
    for (int it = 0; it < 8; it++) {
        int j = wtid + it * 128;
        int jf = j, ji = j + 1024, jo = j + 2048, jc = j + 3072;
        float gf = (__half2float(sgh[wg][jf]) - mu1) * rs1 * ln1g[jf]
                 + (__half2float(sgx[wg][jf]) - mu2) * rs2 * ln2g[jf] + g_bsum[jf];
        float gi = (__half2float(sgh[wg][ji]) - mu1) * rs1 * ln1g[ji]
                 + (__half2float(sgx[wg][ji]) - mu2) * rs2 * ln2g[ji] + g_bsum[ji];
        float go = (__half2float(sgh[wg][jo]) - mu1) * rs1 * ln1g[jo]
                 + (__half2float(sgx[wg][jo]) - mu2) * rs2 * ln2g[jo] + g_bsum[jo];
        float gc = (__half2float(sgh[wg][jc]) - mu1) * rs1 * ln1g[jc]
                 + (__half2float(sgx[wg][jc]) - mu2) * rs2 * ln2g[jc] + g_bsum[jc];

        float cv = sigmoid_fast(gf) * c0[(size_t)b * 1024 + j]
                 + sigmoid_fast(gi) * tanh_fast(gc);
        c1v[it] = cv;
        ogv[it] = go;
        st3.x += cv;
        st3.y += cv * cv;
        c1[(size_t)b * 1024 + j] = cv;
    }
    st3 = warp_reduce4(st3);
    if (lane == 0) red3[wg][wrp] = st3;
    __syncthreads();
    {
        float4 a0 = red3[wg][0], a1 = red3[wg][1], a2 = red3[wg][2], a3 = red3[wg][3];
        st3 = make_float4(a0.x + a1.x + a2.x + a3.x, a0.y + a1.y + a2.y + a3.y,
                          a0.z + a1.z + a2.z + a3.z, a0.w + a1.w + a2.w + a3.w);
    }
    const float invh = 1.0f / 1024.0f;
    float mu3 = st3.x * invh;
    float rs3 = rsqrtf(fmaxf(st3.y * invh - mu3 * mu3, 0.f) + EPS);

    #pragma unroll
    for (int it = 0; it < 8; it++) {
        int j = wtid + it * 128;
        float lnc = (c1v[it] - mu3) * rs3 * ln3g[j] + ln3b[j];
        h1[(size_t)b * 1024 + j] = sigmoid_fast(ogv[it]) * tanh_fast(lnc);
    }
}

// ---------------------------------------------------------------------------
// Launch
// ---------------------------------------------------------------------------
extern "C" void kernel_launch(void* const* d_in, const int* in_sizes, int n_in,
                              void* d_out, int out_size)
{
    const float* x    = (const float*)d_in[0];
    const float* h0   = (const float*)d_in[1];
    const float* c0   = (const float*)d_in[2];
    const float* Wh   = (const float*)d_in[3];
    const float* Wx   = (const float*)d_in[4];
    const float* bias = (const float*)d_in[5];
    const float* ln1g = (const float*)d_in[6];
    const float* ln1b = (const float*)d_in[7];
    const float* ln2g = (const float*)d_in[8];
    const float* ln2b = (const float*)d_in[9];
    const float* ln3g = (const float*)d_in[10];
    const float* ln3b = (const float*)d_in[11];

    float* out = (float*)d_out;
    float* h1 = out;
    float* c1 = out + (size_t)BATCH * KDIM;

    cudaFuncSetAttribute(gemm_mma, cudaFuncAttributeMaxDynamicSharedMemorySize,
                         SMEM_TOTAL);

    convert_all<<<CV_BLOCKS, 256>>>(h0, x, Wh, Wx, ln1b, ln2b, bias);

    dim3 grid(GDIM / BN, BATCH / BM, 2);
    gemm_mma<<<grid, NTHREADS, SMEM_TOTAL>>>();

    epilogue_kernel<<<BATCH / 2, 256>>>(c0, ln1g, ln2g, ln3g, ln3b, h1, c1);
}

// round 14
// speedup vs baseline: 1.4584x; 1.4584x over previous
#include <cuda_runtime.h>
#include <cuda_fp16.h>
#include <math.h>
#include <stdint.h>

// Problem dims (fixed): B=8192, K(=D=H)=1024, 4H=4096
#define BATCH 8192
#define KDIM  1024
#define GDIM  4096

// ---------------------------------------------------------------------------
// Device-global scratch (allocation-free rule)
// ---------------------------------------------------------------------------
__device__ __half g_gh[(size_t)BATCH * GDIM];   // h0 @ Wh (fp16 storage)
__device__ __half g_gx[(size_t)BATCH * GDIM];   // x  @ Wx (fp16 storage)

__device__ __half g_h0f[(size_t)BATCH * KDIM];
__device__ __half g_xf [(size_t)BATCH * KDIM];
__device__ __half g_whf[(size_t)GDIM * KDIM];   // Wt [N][K]
__device__ __half g_wxf[(size_t)GDIM * KDIM];
__device__ float  g_bsum[GDIM];                 // ln1b + ln2b + bias

// ---------------------------------------------------------------------------
// Single merged conversion kernel: 1D grid dispatch.
// ---------------------------------------------------------------------------
#define ACT_BLOCKS 8192
#define WT_BLOCKS  1024
#define CV_BLOCKS  (2 * ACT_BLOCKS + 2 * WT_BLOCKS + 4)

__global__ __launch_bounds__(256)
void convert_all(const float* __restrict__ h0, const float* __restrict__ x,
                 const float* __restrict__ Wh, const float* __restrict__ Wx,
                 const float* __restrict__ ln1b, const float* __restrict__ ln2b,
                 const float* __restrict__ bias)
{
    __shared__ float tile[64][65];
    const int bx = blockIdx.x;
    const int tid = threadIdx.x;

    if (bx < 2 * ACT_BLOCKS) {
        const float* src = (bx < ACT_BLOCKS) ? h0 : x;
        __half* dst = (bx < ACT_BLOCKS) ? g_h0f : g_xf;
        int blk = (bx < ACT_BLOCKS) ? bx : bx - ACT_BLOCKS;
        size_t i = ((size_t)blk * 256 + tid) * 4;
        float4 v = *reinterpret_cast<const float4*>(src + i);
        *reinterpret_cast<__half2*>(dst + i)     = __floats2half2_rn(v.x, v.y);
        *reinterpret_cast<__half2*>(dst + i + 2) = __floats2half2_rn(v.z, v.w);
        return;
    }

    if (bx >= 2 * ACT_BLOCKS + 2 * WT_BLOCKS) {
        int i = (bx - (2 * ACT_BLOCKS + 2 * WT_BLOCKS)) * 1024 + tid * 4;
        float4 a = *reinterpret_cast<const float4*>(ln1b + i);
        float4 b = *reinterpret_cast<const float4*>(ln2b + i);
        float4 c = *reinterpret_cast<const float4*>(bias + i);
        *reinterpret_cast<float4*>(g_bsum + i) =
            make_float4(a.x + b.x + c.x, a.y + b.y + c.y,
                        a.z + b.z + c.z, a.w + b.w + c.w);
        return;
    }

    const int wtb = bx - 2 * ACT_BLOCKS;
    const float* W = (wtb < WT_BLOCKS) ? Wh : Wx;
    __half* T = (wtb < WT_BLOCKS) ? g_whf : g_wxf;
    const int t = (wtb < WT_BLOCKS) ? wtb : wtb - WT_BLOCKS;
    const int n0 = (t & 63) * 64;
    const int k0 = (t >> 6) * 64;

    #pragma unroll
    for (int it = 0; it < 4; it++) {
        int i = tid + it * 256;
        int r = i >> 4;
        int c4 = i & 15;
        float4 v = *reinterpret_cast<const float4*>(
            &W[(size_t)(k0 + r) * GDIM + n0 + c4 * 4]);
        tile[r][c4 * 4 + 0] = v.x;
        tile[r][c4 * 4 + 1] = v.y;
        tile[r][c4 * 4 + 2] = v.z;
        tile[r][c4 * 4 + 3] = v.w;
    }
    __syncthreads();
    #pragma unroll
    for (int it = 0; it < 8; it++) {
        int i = tid + it * 256;
        int n = i >> 5;
        int k2 = i & 31;
        __half2 hv = __floats2half2_rn(tile[k2 * 2][n], tile[k2 * 2 + 1][n]);
        *reinterpret_cast<__half2*>(&T[(size_t)(n0 + n) * KDIM + k0 + k2 * 2]) = hv;
    }
}

// ---------------------------------------------------------------------------
// mma.sync fp16 GEMM — EXACT R12 mainloop ordering (best: 468 us):
// CTA 128x128, 8 warps (32x64), BK=64, 3-stage cp.async, ONE barrier/iter,
// 2 CTAs/SM. load_stage issued BEFORE fragment loads (keeps live ranges short).
// ---------------------------------------------------------------------------
#define BM 128
#define BN 128
#define BK 64
#define KTILES (KDIM / BK)      // 16
#define NTHREADS 256
#define NSTAGES 3

#define ROWB 144
#define T_A 0
#define T_B (128 * ROWB)
#define STAGE (2 * 128 * ROWB)   // 36864
#define SMEM_TOTAL (NSTAGES * STAGE)   // 110592 -> 2 CTAs/SM

__device__ __forceinline__ uint32_t smem_u32(const void* p) {
    return (uint32_t)__cvta_generic_to_shared(p);
}
__device__ __forceinline__ void cp16(uint32_t dst, const void* src) {
    asm volatile("cp.async.cg.shared.global [%0], [%1], 16;\n" :: "r"(dst), "l"(src));
}
__device__ __forceinline__ void ldsm4(uint32_t* r, uint32_t addr) {
    asm volatile("ldmatrix.sync.aligned.m8n8.x4.shared.b16 {%0,%1,%2,%3}, [%4];\n"
                 : "=r"(r[0]), "=r"(r[1]), "=r"(r[2]), "=r"(r[3]) : "r"(addr));
}
__device__ __forceinline__ void mma16816(float* d, const uint32_t* a, const uint32_t* b) {
    asm volatile(
        "mma.sync.aligned.m16n8k16.row.col.f32.f16.f16.f32 "
        "{%0,%1,%2,%3}, {%4,%5,%6,%7}, {%8,%9}, {%0,%1,%2,%3};\n"
        : "+f"(d[0]), "+f"(d[1]), "+f"(d[2]), "+f"(d[3])
        : "r"(a[0]), "r"(a[1]), "r"(a[2]), "r"(a[3]), "r"(b[0]), "r"(b[1]));
}

__device__ __forceinline__ void load_stage(uint32_t sb, int buf,
                                           const __half* A, const __half* B,
                                           int mBase, int nBase, int k0, int tid)
{
    uint32_t st = sb + buf * STAGE;
    #pragma unroll
    for (int it = 0; it < 2048 / NTHREADS; it++) {
        int i = tid + it * NTHREADS;
        int t = i >> 10;
        int j = i & 1023;
        int row = j >> 3;
        int c = j & 7;
        const __half* src;
        uint32_t toff;
        if (t == 0) { src = A + (size_t)(mBase + row) * KDIM + k0 + c * 8; toff = T_A; }
        else        { src = B + (size_t)(nBase + row) * KDIM + k0 + c * 8; toff = T_B; }
        cp16(st + toff + (uint32_t)(row * ROWB + c * 16), src);
    }
}

#define LOAD_B(p, ksv, hv) do {                                                   \
    uint32_t r[4];                                                                \
    ldsm4(r, st + T_B + bOff + (uint32_t)(((hv) * 2 + 0) * 16 * ROWB) + (ksv) * 32); \
    bf[p][0][0] = r[0]; bf[p][0][1] = r[1]; bf[p][1][0] = r[2]; bf[p][1][1] = r[3]; \
    ldsm4(r, st + T_B + bOff + (uint32_t)(((hv) * 2 + 1) * 16 * ROWB) + (ksv) * 32); \
    bf[p][2][0] = r[0]; bf[p][2][1] = r[1]; bf[p][3][0] = r[2]; bf[p][3][1] = r[3]; \
} while (0)

__global__ __launch_bounds__(NTHREADS, 2)
void gemm_mma()
{
    extern __shared__ char smem[];
    const int which = blockIdx.z;
    const __half *A, *B;
    __half* C;
    if (which == 0) { A = g_h0f; B = g_whf; C = g_gh; }
    else            { A = g_xf;  B = g_wxf; C = g_gx; }

    const int nBase = blockIdx.x * BN;
    const int mBase = blockIdx.y * BM;
    const int tid  = threadIdx.x;
    const int lane = tid & 31;
    const int wid  = tid >> 5;
    const int wm   = wid & 3;
    const int wn   = wid >> 2;
    uint32_t sb = smem_u32(smem);

    const uint32_t aOff = (uint32_t)((wm * 32 + (lane & 15)) * ROWB + (lane >> 4) * 16);
    const uint32_t bRow = (uint32_t)(wn * 64 + ((lane >> 4) << 3) + (lane & 7));
    const uint32_t bOff = bRow * ROWB + ((lane >> 3) & 1) * 16;

    float acc[2][8][4];
    #pragma unroll
    for (int mi = 0; mi < 2; mi++)
        #pragma unroll
        for (int ni = 0; ni < 8; ni++)
            #pragma unroll
            for (int q = 0; q < 4; q++)
                acc[mi][ni][q] = 0.0f;

    load_stage(sb, 0, A, B, mBase, nBase, 0,  tid);
    asm volatile("cp.async.commit_group;" ::: "memory");
    load_stage(sb, 1, A, B, mBase, nBase, BK, tid);
    asm volatile("cp.async.commit_group;" ::: "memory");

    int buf = 0;
    for (int k = 0; k < KTILES; k++) {
        if (k < KTILES - 1)
            asm volatile("cp.async.wait_group 1;" ::: "memory");
        else
            asm volatile("cp.async.wait_group 0;" ::: "memory");
        __syncthreads();

        if (k + 2 < KTILES) {
            int nb = buf + 2; if (nb >= 3) nb -= 3;
            load_stage(sb, nb, A, B, mBase, nBase, (k + 2) * BK, tid);
            asm volatile("cp.async.commit_group;" ::: "memory");
        }

        uint32_t st = sb + buf * STAGE;

        uint32_t af[2][2][4];
        uint32_t bf[2][4][2];

        ldsm4(af[0][0], st + T_A + aOff);
        ldsm4(af[0][1], st + T_A + aOff + 16 * ROWB);
        LOAD_B(0, 0, 0);

        #pragma unroll
        for (int s = 0; s < 8; s++) {
            const int ks = s >> 1;
            const int h  = s & 1;
            const int cur = s & 1;
            if (s < 7)
                LOAD_B((s + 1) & 1, (s + 1) >> 1, (s + 1) & 1);
            if (h == 0 && ks < 3) {
                ldsm4(af[(ks + 1) & 1][0], st + T_A + aOff + (ks + 1) * 32);
                ldsm4(af[(ks + 1) & 1][1], st + T_A + aOff + 16 * ROWB + (ks + 1) * 32);
            }
            #pragma unroll
            for (int mi = 0; mi < 2; mi++)
                #pragma unroll
                for (int nj = 0; nj < 4; nj++)
                    mma16816(acc[mi][h * 4 + nj], af[ks & 1][mi], bf[cur][nj]);
        }

        buf++; if (buf >= 3) buf -= 3;
    }

    #pragma unroll
    for (int mi = 0; mi < 2; mi++) {
        #pragma unroll
        for (int ni = 0; ni < 8; ni++) {
            int row = mBase + wm * 32 + mi * 16 + (lane >> 2);
            int col = nBase + wn * 64 + ni * 8 + (lane & 3) * 2;
            __half2 v0 = __floats2half2_rn(acc[mi][ni][0], acc[mi][ni][1]);
            __half2 v1 = __floats2half2_rn(acc[mi][ni][2], acc[mi][ni][3]);
            *reinterpret_cast<__half2*>(C + (size_t)row * GDIM + col) = v0;
            *reinterpret_cast<__half2*>(C + (size_t)(row + 8) * GDIM + col) = v1;
        }
    }
}

// ---------------------------------------------------------------------------
// Fused LSTM epilogue: 2 rows/block, 1 barrier per reduction, tanh.approx,
// folded bias (bsum) -> 3 param arrays instead of 5.
// ---------------------------------------------------------------------------
__device__ __forceinline__ float tanh_fast(float x) {
    float y;
    asm("tanh.approx.f32 %0, %1;" : "=f"(y) : "f"(x));
    return y;
}
__device__ __forceinline__ float sigmoid_fast(float x) {
    return fmaf(0.5f, tanh_fast(0.5f * x), 0.5f);
}

__device__ __forceinline__ float4 warp_reduce4(float4 v) {
    #pragma unroll
    for (int o = 16; o > 0; o >>= 1) {
        v.x += __shfl_down_sync(0xffffffffu, v.x, o);
        v.y += __shfl_down_sync(0xffffffffu, v.y, o);
        v.z += __shfl_down_sync(0xffffffffu, v.z, o);
        v.w += __shfl_down_sync(0xffffffffu, v.w, o);
    }
    return v;
}

__global__ __launch_bounds__(256, 4)
void epilogue_kernel(const float* __restrict__ c0,
                     const float* __restrict__ ln1g,
                     const float* __restrict__ ln2g,
                     const float* __restrict__ ln3g, const float* __restrict__ ln3b,
                     float* __restrict__ h1, float* __restrict__ c1)
{
    __shared__ __half sgh[2][GDIM];
    __shared__ __half sgx[2][GDIM];
    __shared__ float4 red[2][4];
    __shared__ float4 red3[2][4];

    const int tid  = threadIdx.x;
    const int wg   = tid >> 7;
    const int wtid = tid & 127;
    const int lane = tid & 31;
    const int wrp  = wtid >> 5;
    const int b    = blockIdx.x * 2 + wg;

    const uint4* __restrict__ ghr = reinterpret_cast<const uint4*>(g_gh + (size_t)b * GDIM);
    const uint4* __restrict__ gxr = reinterpret_cast<const uint4*>(g_gx + (size_t)b * GDIM);

    const float EPS = 1e-5f;

    float4 st = make_float4(0.f, 0.f, 0.f, 0.f);
    #pragma unroll
    for (int it = 0; it < 4; it++) {
        int i = wtid + it * 128;
        uint4 v = ghr[i];
        uint4 w = gxr[i];
        *reinterpret_cast<uint4*>(&sgh[wg][i * 8]) = v;
        *reinterpret_cast<uint4*>(&sgx[wg][i * 8]) = w;
        const __half2* vh = reinterpret_cast<const __half2*>(&v);
        const __half2* wh = reinterpret_cast<const __half2*>(&w);
        #pragma unroll
        for (int q = 0; q < 4; q++) {
            float2 a = __half22float2(vh[q]);
            float2 bb = __half22float2(wh[q]);
            st.x += a.x + a.y;
            st.y += a.x * a.x + a.y * a.y;
            st.z += bb.x + bb.y;
            st.w += bb.x * bb.x + bb.y * bb.y;
        }
    }
    st = warp_reduce4(st);
    if (lane == 0) red[wg][wrp] = st;
    __syncthreads();
    {
        float4 a0 = red[wg][0], a1 = red[wg][1], a2 = red[wg][2], a3 = red[wg][3];
        st = make_float4(a0.x + a1.x + a2.x + a3.x, a0.y + a1.y + a2.y + a3.y,
                         a0.z + a1.z + a2.z + a3.z, a0.w + a1.w + a2.w + a3.w);
    }
    const float inv4h = 1.0f / (float)GDIM;
    float mu1 = st.x * inv4h;
    float rs1 = rsqrtf(fmaxf(st.y * inv4h - mu1 * mu1, 0.f) + EPS);
    float mu2 = st.z * inv4h;
    float rs2 = rsqrtf(fmaxf(st.w * inv4h - mu2 * mu2, 0.f) + EPS);

    float c1v[8], ogv[8];
    float4 st3 = make_float4(0.f, 0.f, 0.f, 0.f);
    #pragma unroll
    for (int it = 0; it < 8; it++) {
        int j = wtid + it * 128;
        int jf = j, ji = j + 1024, jo = j + 2048, jc = j + 3072;
        float gf = (__half2float(sgh[wg][jf]) - mu1) * rs1 * ln1g[jf]
                 + (__half2float(sgx[wg][jf]) - mu2) * rs2 * ln2g[jf] + g_bsum[jf];
        float gi = (__half2float(sgh[wg][ji]) - mu1) * rs1 * ln1g[ji]
                 + (__half2float(sgx[wg][ji]) - mu2) * rs2 * ln2g[ji] + g_bsum[ji];
        float go = (__half2float(sgh[wg][jo]) - mu1) * rs1 * ln1g[jo]
                 + (__half2float(sgx[wg][jo]) - mu2) * rs2 * ln2g[jo] + g_bsum[jo];
        float gc = (__half2float(sgh[wg][jc]) - mu1) * rs1 * ln1g[jc]
                 + (__half2float(sgx[wg][jc]) - mu2) * rs2 * ln2g[jc] + g_bsum[jc];

        float cv = sigmoid_fast(gf) * c0[(size_t)b * 1024 + j]
                 + sigmoid_fast(gi) * tanh_fast(gc);
        c1v[it] = cv;
        ogv[it] = go;
        st3.x += cv;
        st3.y += cv * cv;
        c1[(size_t)b * 1024 + j] = cv;
    }
    st3 = warp_reduce4(st3);
    if (lane == 0) red3[wg][wrp] = st3;
    __syncthreads();
    {
        float4 a0 = red3[wg][0], a1 = red3[wg][1], a2 = red3[wg][2], a3 = red3[wg][3];
        st3 = make_float4(a0.x + a1.x + a2.x + a3.x, a0.y + a1.y + a2.y + a3.y,
                          a0.z + a1.z + a2.z + a3.z, a0.w + a1.w + a2.w + a3.w);
    }
    const float invh = 1.0f / 1024.0f;
    float mu3 = st3.x * invh;
    float rs3 = rsqrtf(fmaxf(st3.y * invh - mu3 * mu3, 0.f) + EPS);

    #pragma unroll
    for (int it = 0; it < 8; it++) {
        int j = wtid + it * 128;
        float lnc = (c1v[it] - mu3) * rs3 * ln3g[j] + ln3b[j];
        h1[(size_t)b * 1024 + j] = sigmoid_fast(ogv[it]) * tanh_fast(lnc);
    }
}

// ---------------------------------------------------------------------------
// Launch
// ---------------------------------------------------------------------------
extern "C" void kernel_launch(void* const* d_in, const int* in_sizes, int n_in,
                              void* d_out, int out_size)
{
    const float* x    = (const float*)d_in[0];
    const float* h0   = (const float*)d_in[1];
    const float* c0   = (const float*)d_in[2];
    const float* Wh   = (const float*)d_in[3];
    const float* Wx   = (const float*)d_in[4];
    const float* bias = (const float*)d_in[5];
    const float* ln1g = (const float*)d_in[6];
    const float* ln1b = (const float*)d_in[7];
    const float* ln2g = (const float*)d_in[8];
    const float* ln2b = (const float*)d_in[9];
    const float* ln3g = (const float*)d_in[10];
    const float* ln3b = (const float*)d_in[11];

    float* out = (float*)d_out;
    float* h1 = out;
    float* c1 = out + (size_t)BATCH * KDIM;

    cudaFuncSetAttribute(gemm_mma, cudaFuncAttributeMaxDynamicSharedMemorySize,
                         SMEM_TOTAL);

    convert_all<<<CV_BLOCKS, 256>>>(h0, x, Wh, Wx, ln1b, ln2b, bias);

    dim3 grid(GDIM / BN, BATCH / BM, 2);
    gemm_mma<<<grid, NTHREADS, SMEM_TOTAL>>>();

    epilogue_kernel<<<BATCH / 2, 256>>>(c0, ln1g, ln2g, ln3g, ln3b, h1, c1);
}